// round 6
// baseline (speedup 1.0000x reference)
#include <cuda_runtime.h>

#define DM 768
#define NH 12
#define DKH 64
#define SQ 4096
#define NB 2
#define NT (NB * SQ)   // 8192 tokens

// Scratch (allocation-free rule: __device__ globals)
__device__ float g_q[(size_t)NT * DM];
__device__ float g_k[(size_t)NT * DM];
__device__ float g_v[(size_t)NT * DM];
__device__ float g_att[(size_t)NT * DM];

typedef unsigned long long u64;

// packed f32x2 fma: d = a*b + d (elementwise on lo/hi lanes)
__device__ __forceinline__ void ffma2(u64& d, u64 a, u64 b) {
    asm("fma.rn.f32x2 %0, %1, %2, %0;" : "+l"(d) : "l"(a), "l"(b));
}
// horizontal add of a packed pair
__device__ __forceinline__ float hadd2(u64 v) {
    unsigned lo, hi;
    asm("mov.b64 {%0, %1}, %2;" : "=r"(lo), "=r"(hi) : "l"(v));
    return __uint_as_float(lo) + __uint_as_float(hi);
}

__device__ __forceinline__ float redmax16(float v) {
    v = fmaxf(v, __shfl_xor_sync(0xffffffffu, v, 1));
    v = fmaxf(v, __shfl_xor_sync(0xffffffffu, v, 2));
    v = fmaxf(v, __shfl_xor_sync(0xffffffffu, v, 4));
    v = fmaxf(v, __shfl_xor_sync(0xffffffffu, v, 8));
    return v;
}
__device__ __forceinline__ float redsum16(float v) {
    v += __shfl_xor_sync(0xffffffffu, v, 1);
    v += __shfl_xor_sync(0xffffffffu, v, 2);
    v += __shfl_xor_sync(0xffffffffu, v, 4);
    v += __shfl_xor_sync(0xffffffffu, v, 8);
    return v;
}

// ---------------------------------------------------------------------------
// C[M,N] = A[M,K] @ W[N,K]^T + bias[N], M=8192, N=K=768.
// Tile 128x64, BK=32, 256 threads, per-thread 8x4 outputs.
// Packed over k: acc2[i][j] holds (even-k partial, odd-k partial).
// Both smem tiles are natural row-major copies of gmem (k contiguous).
// ---------------------------------------------------------------------------
__global__ __launch_bounds__(256)
void gemm_bias_kernel(const float* __restrict__ A, const float* __restrict__ W,
                      const float* __restrict__ bias, float* __restrict__ C)
{
    __shared__ float As[128][36];   // [m][k] row-major, +4 pad
    __shared__ float Ws[64][36];    // [n][k] row-major
    const int tid = threadIdx.x;
    const int tx = tid & 15, ty = tid >> 4;
    const int m0 = blockIdx.y << 7, n0 = blockIdx.x << 6;

    const int ar = tid >> 1, ac = (tid & 1) << 4;   // A: 2 thr/row, 16 cols each
    const int wr = tid >> 2, wc = (tid & 3) << 3;   // W: 4 thr/row, 8 cols each
    const float* Ap = A + (size_t)(m0 + ar) * DM + ac;
    const float* Wp = W + (size_t)(n0 + wr) * DM + wc;

    u64 acc2[8][4] = {};

    for (int k0 = 0; k0 < DM; k0 += 32) {
        float4 a0 = *(const float4*)(Ap + k0 + 0);
        float4 a1 = *(const float4*)(Ap + k0 + 4);
        float4 a2 = *(const float4*)(Ap + k0 + 8);
        float4 a3 = *(const float4*)(Ap + k0 + 12);
        float4 w0 = *(const float4*)(Wp + k0 + 0);
        float4 w1 = *(const float4*)(Wp + k0 + 4);
        __syncthreads();
        *(float4*)&As[ar][ac + 0]  = a0;
        *(float4*)&As[ar][ac + 4]  = a1;
        *(float4*)&As[ar][ac + 8]  = a2;
        *(float4*)&As[ar][ac + 12] = a3;
        *(float4*)&Ws[wr][wc + 0]  = w0;
        *(float4*)&Ws[wr][wc + 4]  = w1;
        __syncthreads();
        #pragma unroll
        for (int kk = 0; kk < 32; kk += 4) {
            ulonglong2 av[8], bv[4];
            #pragma unroll
            for (int i = 0; i < 8; i++)
                av[i] = *(const ulonglong2*)&As[(ty << 3) + i][kk];
            #pragma unroll
            for (int j = 0; j < 4; j++)
                bv[j] = *(const ulonglong2*)&Ws[(tx << 2) + j][kk];
            #pragma unroll
            for (int i = 0; i < 8; i++)
                #pragma unroll
                for (int j = 0; j < 4; j++) {
                    ffma2(acc2[i][j], av[i].x, bv[j].x);
                    ffma2(acc2[i][j], av[i].y, bv[j].y);
                }
        }
    }

    float4 b4 = *(const float4*)(bias + n0 + (tx << 2));
    #pragma unroll
    for (int i = 0; i < 8; i++) {
        float4 r;
        r.x = hadd2(acc2[i][0]) + b4.x;
        r.y = hadd2(acc2[i][1]) + b4.y;
        r.z = hadd2(acc2[i][2]) + b4.z;
        r.w = hadd2(acc2[i][3]) + b4.w;
        *(float4*)&C[(size_t)(m0 + (ty << 3) + i) * DM + n0 + (tx << 2)] = r;
    }
}

// ---------------------------------------------------------------------------
// Flash attention fp32 with packed f32x2 math.
// CTA = 128 queries of one (b,h); KV tile = 64.
// Layouts (all row-major, natural except Vt):
//   Qs[128][68] = Q rows (pre-scaled), Ks[64][68] = K rows,
//   Vt[64][68]  = V transposed [d][kv],  Ps[128][68] = P rows.
// S packs over d (Q,K pairs natural); PV packs over c (P,Vt pairs natural).
// ---------------------------------------------------------------------------
#define QS_OFF 0
#define KS_OFF (128 * 68)
#define VT_OFF (128 * 68 + 64 * 68)
#define PS_OFF (128 * 68 + 2 * 64 * 68)
#define FL_SMEM ((2 * 128 * 68 + 2 * 64 * 68) * 4)   // 104,448 B

__global__ __launch_bounds__(256)
void flash_kernel(const float* __restrict__ q, const float* __restrict__ k,
                  const float* __restrict__ v, float* __restrict__ o)
{
    extern __shared__ float sm[];
    float (*Qs)[68] = (float(*)[68])(sm + QS_OFF);   // [128][68]
    float (*Ks)[68] = (float(*)[68])(sm + KS_OFF);   // [64][68]
    float (*Vt)[68] = (float(*)[68])(sm + VT_OFF);   // [64][68]  (d-major)
    float (*Ps)[68] = (float(*)[68])(sm + PS_OFF);   // [128][68]

    const int tid = threadIdx.x;
    const int tx = tid & 15, ty = tid >> 4;
    const int bh = blockIdx.y;
    const int b = bh / NH, h = bh - b * NH;
    const int q0 = blockIdx.x << 7;

    const float* qb = q + (size_t)b * SQ * DM + (size_t)h * DKH;
    const float* kb = k + (size_t)b * SQ * DM + (size_t)h * DKH;
    const float* vb = v + (size_t)b * SQ * DM + (size_t)h * DKH;
    float* ob       = o + (size_t)b * SQ * DM + (size_t)h * DKH;

    const int lc = tx << 2;   // 0..60, this thread's 4 head-dims

    // Load Q tile (128 x 64), natural row-major, pre-scaled by 1/8
    #pragma unroll
    for (int it = 0; it < 8; it++) {
        int r = ty + it * 16;
        float4 t = *(const float4*)(qb + (size_t)(q0 + r) * DM + lc);
        t.x *= 0.125f; t.y *= 0.125f; t.z *= 0.125f; t.w *= 0.125f;
        *(float4*)&Qs[r][lc] = t;
    }

    float m_i[8], l_i[8], oacc[8][4];
    #pragma unroll
    for (int i = 0; i < 8; i++) {
        m_i[i] = -1e30f; l_i[i] = 0.f;
        oacc[i][0] = oacc[i][1] = oacc[i][2] = oacc[i][3] = 0.f;
    }

    for (int kv0 = 0; kv0 < SQ; kv0 += 64) {
        // prefetch K/V tile into regs (overlaps the barrier wait)
        float4 rk[4], rv[4];
        #pragma unroll
        for (int it = 0; it < 4; it++) {
            int r = ty + it * 16;
            rk[it] = *(const float4*)(kb + (size_t)(kv0 + r) * DM + lc);
            rv[it] = *(const float4*)(vb + (size_t)(kv0 + r) * DM + lc);
        }
        __syncthreads();   // previous tile's readers of Ks/Vt/Ps done
        #pragma unroll
        for (int it = 0; it < 4; it++) {
            int r = ty + it * 16;
            *(float4*)&Ks[r][lc] = rk[it];           // natural row-major
            Vt[lc + 0][r] = rv[it].x;                // transposed
            Vt[lc + 1][r] = rv[it].y;
            Vt[lc + 2][r] = rv[it].z;
            Vt[lc + 3][r] = rv[it].w;
        }
        __syncthreads();

        // S = Q K^T, packed over d. s2 = (even-d partial, odd-d partial)
        u64 s2[8][4] = {};
        #pragma unroll 2
        for (int d4 = 0; d4 < 64; d4 += 4) {
            ulonglong2 qv[8], kv4[4];
            #pragma unroll
            for (int i = 0; i < 8; i++)
                qv[i] = *(const ulonglong2*)&Qs[(ty << 3) + i][d4];
            #pragma unroll
            for (int j = 0; j < 4; j++)
                kv4[j] = *(const ulonglong2*)&Ks[(tx << 2) + j][d4];
            #pragma unroll
            for (int i = 0; i < 8; i++)
                #pragma unroll
                for (int j = 0; j < 4; j++) {
                    ffma2(s2[i][j], qv[i].x, kv4[j].x);
                    ffma2(s2[i][j], qv[i].y, kv4[j].y);
                }
        }

        // Online softmax (rows reduced across the 16-lane tx group)
        float s[8][4], alpha[8];
        #pragma unroll
        for (int i = 0; i < 8; i++) {
            s[i][0] = hadd2(s2[i][0]); s[i][1] = hadd2(s2[i][1]);
            s[i][2] = hadd2(s2[i][2]); s[i][3] = hadd2(s2[i][3]);
            float mx = fmaxf(fmaxf(s[i][0], s[i][1]), fmaxf(s[i][2], s[i][3]));
            mx = redmax16(mx);
            float mnew = fmaxf(m_i[i], mx);
            alpha[i] = __expf(m_i[i] - mnew);
            m_i[i] = mnew;
            float rsum = 0.f;
            #pragma unroll
            for (int j = 0; j < 4; j++) {
                float p = __expf(s[i][j] - mnew);
                s[i][j] = p;
                rsum += p;
            }
            rsum = redsum16(rsum);
            l_i[i] = l_i[i] * alpha[i] + rsum;
        }

        // Store P row-major (contiguous across tx -> conflict-free)
        #pragma unroll
        for (int i = 0; i < 8; i++) {
            float4 p4;
            p4.x = s[i][0]; p4.y = s[i][1]; p4.z = s[i][2]; p4.w = s[i][3];
            *(float4*)&Ps[(ty << 3) + i][tx << 2] = p4;
        }
        __syncthreads();

        // O_tile = P V, packed over c. pv2 = (even-c partial, odd-c partial)
        u64 pv2[8][4] = {};
        #pragma unroll 2
        for (int c4 = 0; c4 < 64; c4 += 4) {
            ulonglong2 pvq[8], vv[4];
            #pragma unroll
            for (int i = 0; i < 8; i++)
                pvq[i] = *(const ulonglong2*)&Ps[(ty << 3) + i][c4];
            #pragma unroll
            for (int j = 0; j < 4; j++)
                vv[j] = *(const ulonglong2*)&Vt[(tx << 2) + j][c4];
            #pragma unroll
            for (int i = 0; i < 8; i++)
                #pragma unroll
                for (int j = 0; j < 4; j++) {
                    ffma2(pv2[i][j], pvq[i].x, vv[j].x);
                    ffma2(pv2[i][j], pvq[i].y, vv[j].y);
                }
        }

        // merge: oacc = oacc*alpha + tile contribution
        #pragma unroll
        for (int i = 0; i < 8; i++)
            #pragma unroll
            for (int j = 0; j < 4; j++)
                oacc[i][j] = fmaf(oacc[i][j], alpha[i], hadd2(pv2[i][j]));
    }

    // Normalize + write combined layout (B,S,H*dk)
    #pragma unroll
    for (int i = 0; i < 8; i++) {
        float inv = 1.0f / l_i[i];
        float4 r;
        r.x = oacc[i][0] * inv; r.y = oacc[i][1] * inv;
        r.z = oacc[i][2] * inv; r.w = oacc[i][3] * inv;
        *(float4*)(ob + (size_t)(q0 + (ty << 3) + i) * DM + lc) = r;
    }
}

// ---------------------------------------------------------------------------
extern "C" void kernel_launch(void* const* d_in, const int* in_sizes, int n_in,
                              void* d_out, int out_size)
{
    const float* Q  = (const float*)d_in[0];
    const float* K  = (const float*)d_in[1];
    const float* V  = (const float*)d_in[2];
    const float* Wq = (const float*)d_in[3];
    const float* bq = (const float*)d_in[4];
    const float* Wk = (const float*)d_in[5];
    const float* bk = (const float*)d_in[6];
    const float* Wv = (const float*)d_in[7];
    const float* bv = (const float*)d_in[8];
    const float* Wo = (const float*)d_in[9];
    const float* bo = (const float*)d_in[10];
    float* out = (float*)d_out;

    float *gq, *gk, *gv, *ga;
    cudaGetSymbolAddress((void**)&gq, g_q);
    cudaGetSymbolAddress((void**)&gk, g_k);
    cudaGetSymbolAddress((void**)&gv, g_v);
    cudaGetSymbolAddress((void**)&ga, g_att);

    cudaFuncSetAttribute(flash_kernel,
                         cudaFuncAttributeMaxDynamicSharedMemorySize, FL_SMEM);

    dim3 gg(DM / 64, NT / 128);    // (12, 64)
    gemm_bias_kernel<<<gg, 256>>>(Q, Wq, bq, gq);
    gemm_bias_kernel<<<gg, 256>>>(K, Wk, bk, gk);
    gemm_bias_kernel<<<gg, 256>>>(V, Wv, bv, gv);

    dim3 fg(SQ / 128, NB * NH);    // (32, 24)
    flash_kernel<<<fg, 256, FL_SMEM>>>(gq, gk, gv, ga);

    gemm_bias_kernel<<<gg, 256>>>(ga, Wo, bo, out);
}

// round 7
// speedup vs baseline: 1.5938x; 1.5938x over previous
#include <cuda_runtime.h>

#define DM 768
#define NH 12
#define DKH 64
#define SQ 4096
#define NB 2
#define NT (NB * SQ)   // 8192 tokens

// Scratch (allocation-free rule: __device__ globals)
__device__ float g_q[(size_t)NT * DM];
__device__ float g_k[(size_t)NT * DM];
__device__ float g_v[(size_t)NT * DM];
__device__ float g_att[(size_t)NT * DM];

typedef unsigned long long u64;

// packed f32x2 fma: d = a*b + d (elementwise on lo/hi lanes)
__device__ __forceinline__ void ffma2(u64& d, u64 a, u64 b) {
    asm("fma.rn.f32x2 %0, %1, %2, %0;" : "+l"(d) : "l"(a), "l"(b));
}
__device__ __forceinline__ float hadd2(u64 v) {
    unsigned lo, hi;
    asm("mov.b64 {%0, %1}, %2;" : "=r"(lo), "=r"(hi) : "l"(v));
    return __uint_as_float(lo) + __uint_as_float(hi);
}

__device__ __forceinline__ float redmax16(float v) {
    v = fmaxf(v, __shfl_xor_sync(0xffffffffu, v, 1));
    v = fmaxf(v, __shfl_xor_sync(0xffffffffu, v, 2));
    v = fmaxf(v, __shfl_xor_sync(0xffffffffu, v, 4));
    v = fmaxf(v, __shfl_xor_sync(0xffffffffu, v, 8));
    return v;
}
__device__ __forceinline__ float redsum16(float v) {
    v += __shfl_xor_sync(0xffffffffu, v, 1);
    v += __shfl_xor_sync(0xffffffffu, v, 2);
    v += __shfl_xor_sync(0xffffffffu, v, 4);
    v += __shfl_xor_sync(0xffffffffu, v, 8);
    return v;
}

// ---------------------------------------------------------------------------
// C[M,N] = A[M,K] @ W[N,K]^T + bias[N], M=8192, N=K=768.
// Tile 128x64, BK=32, 256 threads, per-thread outputs rows 8ty+i, cols tx+16j.
// As[m][k] / Ws[n][k] natural row-major (k contiguous = packing dim).
// A reads broadcast (depend on ty only); W reads rows tx+16j stride 36 -> <=2-way.
// ---------------------------------------------------------------------------
__global__ __launch_bounds__(256)
void gemm_bias_kernel(const float* __restrict__ A, const float* __restrict__ W,
                      const float* __restrict__ bias, float* __restrict__ C)
{
    __shared__ float As[128][36];
    __shared__ float Ws[64][36];
    const int tid = threadIdx.x;
    const int tx = tid & 15, ty = tid >> 4;
    const int m0 = blockIdx.y << 7, n0 = blockIdx.x << 6;

    const int ar = tid >> 1, ac = (tid & 1) << 4;   // A: 2 thr/row, 16 k each
    const int wr = tid >> 2, wc = (tid & 3) << 3;   // W: 4 thr/row, 8 k each
    const float* Ap = A + (size_t)(m0 + ar) * DM + ac;
    const float* Wp = W + (size_t)(n0 + wr) * DM + wc;

    u64 acc2[8][4] = {};

    for (int k0 = 0; k0 < DM; k0 += 32) {
        float4 a0 = *(const float4*)(Ap + k0 + 0);
        float4 a1 = *(const float4*)(Ap + k0 + 4);
        float4 a2 = *(const float4*)(Ap + k0 + 8);
        float4 a3 = *(const float4*)(Ap + k0 + 12);
        float4 w0 = *(const float4*)(Wp + k0 + 0);
        float4 w1 = *(const float4*)(Wp + k0 + 4);
        __syncthreads();
        *(float4*)&As[ar][ac + 0]  = a0;   // (36*ar+ac)%4==0 -> 16B aligned
        *(float4*)&As[ar][ac + 4]  = a1;
        *(float4*)&As[ar][ac + 8]  = a2;
        *(float4*)&As[ar][ac + 12] = a3;
        *(float4*)&Ws[wr][wc + 0]  = w0;
        *(float4*)&Ws[wr][wc + 4]  = w1;
        __syncthreads();
        #pragma unroll
        for (int kk = 0; kk < 32; kk += 4) {
            ulonglong2 av[8];
            u64 wv[4][2];
            #pragma unroll
            for (int i = 0; i < 8; i++)        // broadcast across tx
                av[i] = *(const ulonglong2*)&As[(ty << 3) + i][kk];
            #pragma unroll
            for (int j = 0; j < 4; j++) {      // rows tx+16j, <=2-way
                wv[j][0] = *(const u64*)&Ws[tx + (j << 4)][kk];
                wv[j][1] = *(const u64*)&Ws[tx + (j << 4)][kk + 2];
            }
            #pragma unroll
            for (int i = 0; i < 8; i++)
                #pragma unroll
                for (int j = 0; j < 4; j++) {
                    ffma2(acc2[i][j], av[i].x, wv[j][0]);
                    ffma2(acc2[i][j], av[i].y, wv[j][1]);
                }
        }
    }

    float bj[4];
    #pragma unroll
    for (int j = 0; j < 4; j++) bj[j] = bias[n0 + tx + (j << 4)];
    #pragma unroll
    for (int i = 0; i < 8; i++) {
        size_t row = (size_t)(m0 + (ty << 3) + i) * DM + n0;
        #pragma unroll
        for (int j = 0; j < 4; j++)
            C[row + tx + (j << 4)] = hadd2(acc2[i][j]) + bj[j];
    }
}

// ---------------------------------------------------------------------------
// Flash attention fp32, packed f32x2. CTA = 128 queries, KV tile = 64.
// Layouts (row stride 68 floats):
//   Qs[128][68]  Q rows (d contiguous, pre-scaled)   -> broadcast reads
//   Ks[64][68]   K rows (d contiguous)               -> rows tx+16j reads
//   Vt[64][68]   V transposed [d][c] (c contiguous)  -> rows tx+16j reads
//   Ps[128][68]  P rows (c contiguous)               -> broadcast reads
// ---------------------------------------------------------------------------
#define FSTR 68
#define QS_OFF 0
#define KS_OFF (128 * FSTR)
#define VT_OFF ((128 + 64) * FSTR)
#define PS_OFF ((128 + 128) * FSTR)
#define FL_SMEM (384 * FSTR * 4)   // 104448 B

__global__ __launch_bounds__(256)
void flash_kernel(const float* __restrict__ q, const float* __restrict__ k,
                  const float* __restrict__ v, float* __restrict__ o)
{
    extern __shared__ float sm[];
    float (*Qs)[FSTR] = (float(*)[FSTR])(sm + QS_OFF);
    float (*Ks)[FSTR] = (float(*)[FSTR])(sm + KS_OFF);
    float (*Vt)[FSTR] = (float(*)[FSTR])(sm + VT_OFF);
    float (*Ps)[FSTR] = (float(*)[FSTR])(sm + PS_OFF);

    const int tid = threadIdx.x;
    const int tx = tid & 15, ty = tid >> 4;
    const int bh = blockIdx.y;
    const int b = bh / NH, h = bh - b * NH;
    const int q0 = blockIdx.x << 7;

    const float* qb = q + (size_t)b * SQ * DM + (size_t)h * DKH;
    const float* kb = k + (size_t)b * SQ * DM + (size_t)h * DKH;
    const float* vb = v + (size_t)b * SQ * DM + (size_t)h * DKH;
    float* ob       = o + (size_t)b * SQ * DM + (size_t)h * DKH;

    const int lc = tx << 2;   // gmem load cols

    // Load Q (128 x 64), natural rows, pre-scaled by 1/8
    #pragma unroll
    for (int it = 0; it < 8; it++) {
        int r = ty + it * 16;
        float4 t = *(const float4*)(qb + (size_t)(q0 + r) * DM + lc);
        t.x *= 0.125f; t.y *= 0.125f; t.z *= 0.125f; t.w *= 0.125f;
        *(float4*)&Qs[r][lc] = t;   // (68r+4tx)%4==0 -> aligned
    }

    float m_i[8], l_i[8], oacc[8][4];
    #pragma unroll
    for (int i = 0; i < 8; i++) {
        m_i[i] = -1e30f; l_i[i] = 0.f;
        oacc[i][0] = oacc[i][1] = oacc[i][2] = oacc[i][3] = 0.f;
    }

    for (int kv0 = 0; kv0 < SQ; kv0 += 64) {
        float4 rk[4], rv[4];
        #pragma unroll
        for (int it = 0; it < 4; it++) {
            int r = ty + it * 16;
            rk[it] = *(const float4*)(kb + (size_t)(kv0 + r) * DM + lc);
            rv[it] = *(const float4*)(vb + (size_t)(kv0 + r) * DM + lc);
        }
        __syncthreads();   // prev tile's readers done
        #pragma unroll
        for (int it = 0; it < 4; it++) {
            int r = ty + it * 16;
            *(float4*)&Ks[r][lc] = rk[it];   // natural
            Vt[lc + 0][r] = rv[it].x;        // transposed
            Vt[lc + 1][r] = rv[it].y;
            Vt[lc + 2][r] = rv[it].z;
            Vt[lc + 3][r] = rv[it].w;
        }
        __syncthreads();

        // S = Q K^T packed over d. s2[i][j]: row 8ty+i, col tx+16j
        u64 s2[8][4] = {};
        #pragma unroll 4
        for (int d4 = 0; d4 < 64; d4 += 4) {
            ulonglong2 qv[8];
            u64 ka[4][2];
            #pragma unroll
            for (int i = 0; i < 8; i++)
                qv[i] = *(const ulonglong2*)&Qs[(ty << 3) + i][d4];
            #pragma unroll
            for (int j = 0; j < 4; j++) {
                ka[j][0] = *(const u64*)&Ks[tx + (j << 4)][d4];
                ka[j][1] = *(const u64*)&Ks[tx + (j << 4)][d4 + 2];
            }
            #pragma unroll
            for (int i = 0; i < 8; i++)
                #pragma unroll
                for (int j = 0; j < 4; j++) {
                    ffma2(s2[i][j], qv[i].x, ka[j][0]);
                    ffma2(s2[i][j], qv[i].y, ka[j][1]);
                }
        }

        // Online softmax (row groups across tx lanes)
        float s[8][4], alpha[8];
        #pragma unroll
        for (int i = 0; i < 8; i++) {
            s[i][0] = hadd2(s2[i][0]); s[i][1] = hadd2(s2[i][1]);
            s[i][2] = hadd2(s2[i][2]); s[i][3] = hadd2(s2[i][3]);
            float mx = fmaxf(fmaxf(s[i][0], s[i][1]), fmaxf(s[i][2], s[i][3]));
            mx = redmax16(mx);
            float mnew = fmaxf(m_i[i], mx);
            alpha[i] = __expf(m_i[i] - mnew);
            m_i[i] = mnew;
            float rsum = 0.f;
            #pragma unroll
            for (int j = 0; j < 4; j++) {
                float p = __expf(s[i][j] - mnew);
                s[i][j] = p;
                rsum += p;
            }
            rsum = redsum16(rsum);
            l_i[i] = l_i[i] * alpha[i] + rsum;
        }

        // Store P natural row-major: cols tx+16j -> consecutive across tx
        #pragma unroll
        for (int i = 0; i < 8; i++)
            #pragma unroll
            for (int j = 0; j < 4; j++)
                Ps[(ty << 3) + i][tx + (j << 4)] = s[i][j];
        __syncthreads();

        // O_tile = P V packed over c. outputs: row 8ty+i, d-col tx+16j
        u64 pv2[8][4] = {};
        #pragma unroll 4
        for (int c4 = 0; c4 < 64; c4 += 4) {
            ulonglong2 pq[8];
            u64 va[4][2];
            #pragma unroll
            for (int i = 0; i < 8; i++)
                pq[i] = *(const ulonglong2*)&Ps[(ty << 3) + i][c4];
            #pragma unroll
            for (int j = 0; j < 4; j++) {
                va[j][0] = *(const u64*)&Vt[tx + (j << 4)][c4];
                va[j][1] = *(const u64*)&Vt[tx + (j << 4)][c4 + 2];
            }
            #pragma unroll
            for (int i = 0; i < 8; i++)
                #pragma unroll
                for (int j = 0; j < 4; j++) {
                    ffma2(pv2[i][j], pq[i].x, va[j][0]);
                    ffma2(pv2[i][j], pq[i].y, va[j][1]);
                }
        }

        #pragma unroll
        for (int i = 0; i < 8; i++)
            #pragma unroll
            for (int j = 0; j < 4; j++)
                oacc[i][j] = fmaf(oacc[i][j], alpha[i], hadd2(pv2[i][j]));
    }

    // Normalize + write combined layout (B,S,H*dk); cols tx+16j coalesce per j
    #pragma unroll
    for (int i = 0; i < 8; i++) {
        float inv = 1.0f / l_i[i];
        size_t row = (size_t)(q0 + (ty << 3) + i) * DM;
        #pragma unroll
        for (int j = 0; j < 4; j++)
            ob[row + tx + (j << 4)] = oacc[i][j] * inv;
    }
}

// ---------------------------------------------------------------------------
extern "C" void kernel_launch(void* const* d_in, const int* in_sizes, int n_in,
                              void* d_out, int out_size)
{
    const float* Q  = (const float*)d_in[0];
    const float* K  = (const float*)d_in[1];
    const float* V  = (const float*)d_in[2];
    const float* Wq = (const float*)d_in[3];
    const float* bq = (const float*)d_in[4];
    const float* Wk = (const float*)d_in[5];
    const float* bk = (const float*)d_in[6];
    const float* Wv = (const float*)d_in[7];
    const float* bv = (const float*)d_in[8];
    const float* Wo = (const float*)d_in[9];
    const float* bo = (const float*)d_in[10];
    float* out = (float*)d_out;

    float *gq, *gk, *gv, *ga;
    cudaGetSymbolAddress((void**)&gq, g_q);
    cudaGetSymbolAddress((void**)&gk, g_k);
    cudaGetSymbolAddress((void**)&gv, g_v);
    cudaGetSymbolAddress((void**)&ga, g_att);

    cudaFuncSetAttribute(flash_kernel,
                         cudaFuncAttributeMaxDynamicSharedMemorySize, FL_SMEM);

    dim3 gg(DM / 64, NT / 128);    // (12, 64)
    gemm_bias_kernel<<<gg, 256>>>(Q, Wq, bq, gq);
    gemm_bias_kernel<<<gg, 256>>>(K, Wk, bk, gk);
    gemm_bias_kernel<<<gg, 256>>>(V, Wv, bv, gv);

    dim3 fg(SQ / 128, NB * NH);    // (32, 24)
    flash_kernel<<<fg, 256, FL_SMEM>>>(gq, gk, gv, ga);

    gemm_bias_kernel<<<gg, 256>>>(ga, Wo, bo, out);
}

// round 8
// speedup vs baseline: 3.0649x; 1.9230x over previous
#include <cuda_runtime.h>
#include <cuda_bf16.h>

#define DM 768
#define NH 12
#define DKH 64
#define SQ 4096
#define NB 2
#define NT (NB * SQ)   // 8192 tokens

// Scratch (allocation-free rule: __device__ globals)
__device__ float g_q[(size_t)NT * DM];
__device__ float g_k[(size_t)NT * DM];
__device__ float g_v[(size_t)NT * DM];
__device__ float g_att[(size_t)NT * DM];
__device__ __nv_bfloat16 g_qhi[(size_t)NT * DM], g_qlo[(size_t)NT * DM];
__device__ __nv_bfloat16 g_khi[(size_t)NT * DM], g_klo[(size_t)NT * DM];
__device__ __nv_bfloat16 g_vhi[(size_t)NT * DM], g_vlo[(size_t)NT * DM];

// pack two f32 -> bf16x2 (lo arg -> low half)
__device__ __forceinline__ unsigned pk2(float lo, float hi) {
    unsigned d;
    asm("cvt.rn.bf16x2.f32 %0, %1, %2;" : "=r"(d) : "f"(hi), "f"(lo));
    return d;
}
__device__ __forceinline__ float lo_f32(unsigned u) { return __uint_as_float(u << 16); }
__device__ __forceinline__ float hi_f32(unsigned u) { return __uint_as_float(u & 0xffff0000u); }

// D += A(16x16) * B(16x8), bf16 inputs, f32 accum
__device__ __forceinline__ void mma16816(float* d, const unsigned* a, unsigned b0, unsigned b1) {
    asm volatile(
        "mma.sync.aligned.m16n8k16.row.col.f32.bf16.bf16.f32 "
        "{%0,%1,%2,%3}, {%4,%5,%6,%7}, {%8,%9}, {%0,%1,%2,%3};\n"
        : "+f"(d[0]), "+f"(d[1]), "+f"(d[2]), "+f"(d[3])
        : "r"(a[0]), "r"(a[1]), "r"(a[2]), "r"(a[3]), "r"(b0), "r"(b1));
}

// ---------------------------------------------------------------------------
// GEMM (unchanged from best round): C = A @ W^T + bias, 128x128 tile, 8x8/thr
// ---------------------------------------------------------------------------
__global__ __launch_bounds__(256)
void gemm_bias_kernel(const float* __restrict__ A, const float* __restrict__ W,
                      const float* __restrict__ bias, float* __restrict__ C)
{
    __shared__ float As[16][132];
    __shared__ float Ws[16][132];
    const int tid = threadIdx.x;
    const int tx = tid & 15, ty = tid >> 4;
    const int m0 = blockIdx.y << 7, n0 = blockIdx.x << 7;

    const int lr = tid >> 2;
    const int lc = (tid & 3) << 2;
    const float* Ap = A + (size_t)(m0 + lr) * DM + lc;
    const float* Wp = W + (size_t)(n0 + lr) * DM + lc;

    float acc[8][8] = {};

    for (int k0 = 0; k0 < DM; k0 += 16) {
        float4 av0 = *(const float4*)(Ap + k0);
        float4 av1 = *(const float4*)(Ap + (size_t)64 * DM + k0);
        float4 wv0 = *(const float4*)(Wp + k0);
        float4 wv1 = *(const float4*)(Wp + (size_t)64 * DM + k0);
        __syncthreads();
        As[lc + 0][lr] = av0.x; As[lc + 1][lr] = av0.y;
        As[lc + 2][lr] = av0.z; As[lc + 3][lr] = av0.w;
        As[lc + 0][lr + 64] = av1.x; As[lc + 1][lr + 64] = av1.y;
        As[lc + 2][lr + 64] = av1.z; As[lc + 3][lr + 64] = av1.w;
        Ws[lc + 0][lr] = wv0.x; Ws[lc + 1][lr] = wv0.y;
        Ws[lc + 2][lr] = wv0.z; Ws[lc + 3][lr] = wv0.w;
        Ws[lc + 0][lr + 64] = wv1.x; Ws[lc + 1][lr + 64] = wv1.y;
        Ws[lc + 2][lr + 64] = wv1.z; Ws[lc + 3][lr + 64] = wv1.w;
        __syncthreads();
        #pragma unroll
        for (int kk = 0; kk < 16; kk++) {
            float4 fa0 = *(const float4*)&As[kk][ty << 3];
            float4 fa1 = *(const float4*)&As[kk][(ty << 3) + 4];
            float4 fb0 = *(const float4*)&Ws[kk][tx << 2];
            float4 fb1 = *(const float4*)&Ws[kk][64 + (tx << 2)];
            float a[8] = {fa0.x, fa0.y, fa0.z, fa0.w, fa1.x, fa1.y, fa1.z, fa1.w};
            float b[8] = {fb0.x, fb0.y, fb0.z, fb0.w, fb1.x, fb1.y, fb1.z, fb1.w};
            #pragma unroll
            for (int i = 0; i < 8; i++)
                #pragma unroll
                for (int j = 0; j < 8; j++)
                    acc[i][j] = fmaf(a[i], b[j], acc[i][j]);
        }
    }

    float4 bb0 = *(const float4*)(bias + n0 + (tx << 2));
    float4 bb1 = *(const float4*)(bias + n0 + 64 + (tx << 2));
    #pragma unroll
    for (int i = 0; i < 8; i++) {
        size_t row = (size_t)(m0 + (ty << 3) + i) * DM;
        float4 r0, r1;
        r0.x = acc[i][0] + bb0.x; r0.y = acc[i][1] + bb0.y;
        r0.z = acc[i][2] + bb0.z; r0.w = acc[i][3] + bb0.w;
        r1.x = acc[i][4] + bb1.x; r1.y = acc[i][5] + bb1.y;
        r1.z = acc[i][6] + bb1.z; r1.w = acc[i][7] + bb1.w;
        *(float4*)&C[row + n0 + (tx << 2)] = r0;
        *(float4*)&C[row + n0 + 64 + (tx << 2)] = r1;
    }
}

// ---------------------------------------------------------------------------
// Split fp32 -> (hi, lo) bf16, elementwise, optional scale. x4 vectorized.
// ---------------------------------------------------------------------------
__global__ __launch_bounds__(256)
void split_kernel(const float* __restrict__ x, __nv_bfloat16* __restrict__ hi,
                  __nv_bfloat16* __restrict__ lo, float scale)
{
    int i = blockIdx.x * blockDim.x + threadIdx.x;   // float4 index
    float4 v = ((const float4*)x)[i];
    v.x *= scale; v.y *= scale; v.z *= scale; v.w *= scale;
    unsigned h01 = pk2(v.x, v.y), h23 = pk2(v.z, v.w);
    float r0 = v.x - lo_f32(h01), r1 = v.y - hi_f32(h01);
    float r2 = v.z - lo_f32(h23), r3 = v.w - hi_f32(h23);
    unsigned l01 = pk2(r0, r1), l23 = pk2(r2, r3);
    uint2 hw; hw.x = h01; hw.y = h23;
    uint2 lw; lw.x = l01; lw.y = l23;
    ((uint2*)hi)[i] = hw;
    ((uint2*)lo)[i] = lw;
}

// ---------------------------------------------------------------------------
// Tensor-core flash attention, split-bf16 3-pass mma.
// CTA = 128 queries of one (b,h); 8 warps, warp w owns rows 16w..16w+15.
// KV tile = 64. smem K/V tiles (hi/lo) with 72-bf16 padded rows.
// ---------------------------------------------------------------------------
__global__ __launch_bounds__(256)
void flash_kernel(const __nv_bfloat16* __restrict__ qhi, const __nv_bfloat16* __restrict__ qlo,
                  const __nv_bfloat16* __restrict__ khi, const __nv_bfloat16* __restrict__ klo,
                  const __nv_bfloat16* __restrict__ vhi, const __nv_bfloat16* __restrict__ vlo,
                  float* __restrict__ o)
{
    __shared__ __nv_bfloat16 s_khi[64][72], s_klo[64][72];
    __shared__ __nv_bfloat16 s_vhi[64][72], s_vlo[64][72];

    const int tid = threadIdx.x;
    const int warp = tid >> 5, lane = tid & 31;
    const int g = lane >> 2, t = lane & 3;
    const int bh = blockIdx.y;
    const int b = bh / NH, h = bh - b * NH;
    const int q0 = blockIdx.x << 7;

    const size_t base = (size_t)b * SQ * DM + (size_t)h * DKH;

    // --- Q fragments (hi/lo), loaded once. a0:(row g, k 2t), a1:(g+8), a2:(g,k+8), a3:(g+8,k+8)
    unsigned aQh[4][4], aQl[4][4];
    {
        const unsigned* qh  = (const unsigned*)(qhi + base + (size_t)(q0 + (warp << 4) + g) * DM);
        const unsigned* qh8 = qh + 8 * DM / 2;
        const unsigned* ql  = (const unsigned*)(qlo + base + (size_t)(q0 + (warp << 4) + g) * DM);
        const unsigned* ql8 = ql + 8 * DM / 2;
        #pragma unroll
        for (int kt = 0; kt < 4; kt++) {
            aQh[kt][0] = qh [8 * kt + t];
            aQh[kt][1] = qh8[8 * kt + t];
            aQh[kt][2] = qh [8 * kt + t + 4];
            aQh[kt][3] = qh8[8 * kt + t + 4];
            aQl[kt][0] = ql [8 * kt + t];
            aQl[kt][1] = ql8[8 * kt + t];
            aQl[kt][2] = ql [8 * kt + t + 4];
            aQl[kt][3] = ql8[8 * kt + t + 4];
        }
    }

    float m0 = -1e30f, m1 = -1e30f, l0 = 0.f, l1 = 0.f;
    float oacc[8][4] = {};

    const __nv_bfloat16* kh_g = khi + base;
    const __nv_bfloat16* kl_g = klo + base;
    const __nv_bfloat16* vh_g = vhi + base;
    const __nv_bfloat16* vl_g = vlo + base;

    for (int kv0 = 0; kv0 < SQ; kv0 += 64) {
        __syncthreads();   // prior tile's smem readers done
        // --- load K/V tiles hi/lo (64 rows x 64 bf16 = 8 uint4 per row)
        #pragma unroll
        for (int it = 0; it < 2; it++) {
            int i = tid + it * 256;           // 0..511
            int r = i >> 3, j = i & 7;
            size_t gofs = (size_t)(kv0 + r) * DM;
            *((uint4*)&s_khi[r][0] + j) = *((const uint4*)(kh_g + gofs) + j);
            *((uint4*)&s_klo[r][0] + j) = *((const uint4*)(kl_g + gofs) + j);
            *((uint4*)&s_vhi[r][0] + j) = *((const uint4*)(vh_g + gofs) + j);
            *((uint4*)&s_vlo[r][0] + j) = *((const uint4*)(vl_g + gofs) + j);
        }
        __syncthreads();

        // --- S = Q K^T (3-pass split). s[nt]: accum tile over kv cols 8nt..8nt+7
        float s[8][4] = {};
        #pragma unroll
        for (int kt = 0; kt < 4; kt++)
            #pragma unroll
            for (int nt = 0; nt < 8; nt++) {
                const unsigned* krh = (const unsigned*)&s_khi[8 * nt + g][0];
                const unsigned* krl = (const unsigned*)&s_klo[8 * nt + g][0];
                unsigned bh0 = krh[8 * kt + t], bh1 = krh[8 * kt + t + 4];
                unsigned bl0 = krl[8 * kt + t], bl1 = krl[8 * kt + t + 4];
                mma16816(s[nt], aQh[kt], bh0, bh1);
                mma16816(s[nt], aQh[kt], bl0, bl1);
                mma16816(s[nt], aQl[kt], bh0, bh1);
            }

        // --- online softmax. rows: r0 = g (c0,c1), r1 = g+8 (c2,c3)
        float mx0 = -1e30f, mx1 = -1e30f;
        #pragma unroll
        for (int nt = 0; nt < 8; nt++) {
            mx0 = fmaxf(mx0, fmaxf(s[nt][0], s[nt][1]));
            mx1 = fmaxf(mx1, fmaxf(s[nt][2], s[nt][3]));
        }
        mx0 = fmaxf(mx0, __shfl_xor_sync(0xffffffffu, mx0, 1));
        mx0 = fmaxf(mx0, __shfl_xor_sync(0xffffffffu, mx0, 2));
        mx1 = fmaxf(mx1, __shfl_xor_sync(0xffffffffu, mx1, 1));
        mx1 = fmaxf(mx1, __shfl_xor_sync(0xffffffffu, mx1, 2));
        float mn0 = fmaxf(m0, mx0), mn1 = fmaxf(m1, mx1);
        float al0 = __expf(m0 - mn0), al1 = __expf(m1 - mn1);
        m0 = mn0; m1 = mn1;
        float ls0 = 0.f, ls1 = 0.f;
        #pragma unroll
        for (int nt = 0; nt < 8; nt++) {
            s[nt][0] = __expf(s[nt][0] - mn0); ls0 += s[nt][0];
            s[nt][1] = __expf(s[nt][1] - mn0); ls0 += s[nt][1];
            s[nt][2] = __expf(s[nt][2] - mn1); ls1 += s[nt][2];
            s[nt][3] = __expf(s[nt][3] - mn1); ls1 += s[nt][3];
        }
        ls0 += __shfl_xor_sync(0xffffffffu, ls0, 1);
        ls0 += __shfl_xor_sync(0xffffffffu, ls0, 2);
        ls1 += __shfl_xor_sync(0xffffffffu, ls1, 1);
        ls1 += __shfl_xor_sync(0xffffffffu, ls1, 2);
        l0 = l0 * al0 + ls0;
        l1 = l1 * al1 + ls1;
        #pragma unroll
        for (int nt = 0; nt < 8; nt++) {
            oacc[nt][0] *= al0; oacc[nt][1] *= al0;
            oacc[nt][2] *= al1; oacc[nt][3] *= al1;
        }

        // --- P -> bf16 A-fragments (hi/lo). kt covers kv 16kt..16kt+15 = s tiles 2kt, 2kt+1
        unsigned pah[4][4], pal[4][4];
        #pragma unroll
        for (int kt = 0; kt < 4; kt++) {
            int e = 2 * kt, od = 2 * kt + 1;
            pah[kt][0] = pk2(s[e][0],  s[e][1]);
            pah[kt][1] = pk2(s[e][2],  s[e][3]);
            pah[kt][2] = pk2(s[od][0], s[od][1]);
            pah[kt][3] = pk2(s[od][2], s[od][3]);
            pal[kt][0] = pk2(s[e][0]  - lo_f32(pah[kt][0]), s[e][1]  - hi_f32(pah[kt][0]));
            pal[kt][1] = pk2(s[e][2]  - lo_f32(pah[kt][1]), s[e][3]  - hi_f32(pah[kt][1]));
            pal[kt][2] = pk2(s[od][0] - lo_f32(pah[kt][2]), s[od][1] - hi_f32(pah[kt][2]));
            pal[kt][3] = pk2(s[od][2] - lo_f32(pah[kt][3]), s[od][3] - hi_f32(pah[kt][3]));
        }

        // --- O += P V (3-pass). B[k=kv][n=d] from natural [kv][d] rows: 2x LDS.16 + merge
        #pragma unroll
        for (int kt = 0; kt < 4; kt++) {
            int kr = 16 * kt + 2 * t;
            #pragma unroll
            for (int nt = 0; nt < 8; nt++) {
                int c = 8 * nt + g;
                unsigned vh0a = *(const unsigned short*)&s_vhi[kr][c];
                unsigned vh0b = *(const unsigned short*)&s_vhi[kr + 1][c];
                unsigned vh1a = *(const unsigned short*)&s_vhi[kr + 8][c];
                unsigned vh1b = *(const unsigned short*)&s_vhi[kr + 9][c];
                unsigned vl0a = *(const unsigned short*)&s_vlo[kr][c];
                unsigned vl0b = *(const unsigned short*)&s_vlo[kr + 1][c];
                unsigned vl1a = *(const unsigned short*)&s_vlo[kr + 8][c];
                unsigned vl1b = *(const unsigned short*)&s_vlo[kr + 9][c];
                unsigned bh0 = vh0a | (vh0b << 16);
                unsigned bh1 = vh1a | (vh1b << 16);
                unsigned bl0 = vl0a | (vl0b << 16);
                unsigned bl1 = vl1a | (vl1b << 16);
                mma16816(oacc[nt], pah[kt], bh0, bh1);
                mma16816(oacc[nt], pah[kt], bl0, bl1);
                mma16816(oacc[nt], pal[kt], bh0, bh1);
            }
        }
    }

    // --- epilogue: normalize, write combined layout (B,S,H*dk)
    float inv0 = 1.0f / l0, inv1 = 1.0f / l1;
    float* or0 = o + base + (size_t)(q0 + (warp << 4) + g) * DM;
    float* or1 = or0 + (size_t)8 * DM;
    #pragma unroll
    for (int nt = 0; nt < 8; nt++) {
        float2 w0, w1;
        w0.x = oacc[nt][0] * inv0; w0.y = oacc[nt][1] * inv0;
        w1.x = oacc[nt][2] * inv1; w1.y = oacc[nt][3] * inv1;
        *(float2*)&or0[8 * nt + 2 * t] = w0;
        *(float2*)&or1[8 * nt + 2 * t] = w1;
    }
}

// ---------------------------------------------------------------------------
extern "C" void kernel_launch(void* const* d_in, const int* in_sizes, int n_in,
                              void* d_out, int out_size)
{
    const float* Q  = (const float*)d_in[0];
    const float* K  = (const float*)d_in[1];
    const float* V  = (const float*)d_in[2];
    const float* Wq = (const float*)d_in[3];
    const float* bq = (const float*)d_in[4];
    const float* Wk = (const float*)d_in[5];
    const float* bk = (const float*)d_in[6];
    const float* Wv = (const float*)d_in[7];
    const float* bv = (const float*)d_in[8];
    const float* Wo = (const float*)d_in[9];
    const float* bo = (const float*)d_in[10];
    float* out = (float*)d_out;

    float *gq, *gk, *gv, *ga;
    __nv_bfloat16 *qh, *ql, *kh, *kl, *vh, *vl;
    cudaGetSymbolAddress((void**)&gq, g_q);
    cudaGetSymbolAddress((void**)&gk, g_k);
    cudaGetSymbolAddress((void**)&gv, g_v);
    cudaGetSymbolAddress((void**)&ga, g_att);
    cudaGetSymbolAddress((void**)&qh, g_qhi);
    cudaGetSymbolAddress((void**)&ql, g_qlo);
    cudaGetSymbolAddress((void**)&kh, g_khi);
    cudaGetSymbolAddress((void**)&kl, g_klo);
    cudaGetSymbolAddress((void**)&vh, g_vhi);
    cudaGetSymbolAddress((void**)&vl, g_vlo);

    dim3 gg(DM / 128, NT / 128);   // (6, 64)
    int nsp = (NT * DM) / 4 / 256; // split blocks (float4-granular)

    gemm_bias_kernel<<<gg, 256>>>(Q, Wq, bq, gq);
    split_kernel<<<nsp, 256>>>(gq, qh, ql, 0.125f);   // fold 1/sqrt(dk)
    gemm_bias_kernel<<<gg, 256>>>(K, Wk, bk, gk);
    split_kernel<<<nsp, 256>>>(gk, kh, kl, 1.0f);
    gemm_bias_kernel<<<gg, 256>>>(V, Wv, bv, gv);
    split_kernel<<<nsp, 256>>>(gv, vh, vl, 1.0f);

    dim3 fg(SQ / 128, NB * NH);    // (32, 24)
    flash_kernel<<<fg, 256>>>(qh, ql, kh, kl, vh, vl, ga);

    gemm_bias_kernel<<<gg, 256>>>(ga, Wo, bo, out);
}

// round 12
// speedup vs baseline: 3.9321x; 1.2829x over previous
#include <cuda_runtime.h>
#include <cuda_bf16.h>

#define DM 768
#define NH 12
#define DKH 64
#define SQ 4096
#define NB 2
#define NT (NB * SQ)   // 8192 tokens

// Scratch (allocation-free rule: __device__ globals), all bf16 hi/lo pairs
__device__ __nv_bfloat16 g_iqh[(size_t)NT * DM], g_iql[(size_t)NT * DM];  // input Q
__device__ __nv_bfloat16 g_ikh[(size_t)NT * DM], g_ikl[(size_t)NT * DM];  // input K
__device__ __nv_bfloat16 g_ivh[(size_t)NT * DM], g_ivl[(size_t)NT * DM];  // input V
__device__ __nv_bfloat16 g_wqh[(size_t)DM * DM], g_wql[(size_t)DM * DM];
__device__ __nv_bfloat16 g_wkh[(size_t)DM * DM], g_wkl[(size_t)DM * DM];
__device__ __nv_bfloat16 g_wvh[(size_t)DM * DM], g_wvl[(size_t)DM * DM];
__device__ __nv_bfloat16 g_woh[(size_t)DM * DM], g_wol[(size_t)DM * DM];
__device__ __nv_bfloat16 g_pqh[(size_t)NT * DM], g_pql[(size_t)NT * DM];  // proj q (scaled)
__device__ __nv_bfloat16 g_pkh[(size_t)NT * DM], g_pkl[(size_t)NT * DM];  // proj k
__device__ __nv_bfloat16 g_pvh[(size_t)NT * DM], g_pvl[(size_t)NT * DM];  // proj v
__device__ __nv_bfloat16 g_ath[(size_t)NT * DM], g_atl[(size_t)NT * DM];  // attention out

// pack two f32 -> bf16x2 (first arg -> low half)
__device__ __forceinline__ unsigned pk2(float lo, float hi) {
    unsigned d;
    asm("cvt.rn.bf16x2.f32 %0, %1, %2;" : "=r"(d) : "f"(hi), "f"(lo));
    return d;
}
__device__ __forceinline__ float lo_f32(unsigned u) { return __uint_as_float(u << 16); }
__device__ __forceinline__ float hi_f32(unsigned u) { return __uint_as_float(u & 0xffff0000u); }

// D += A(16x16) * B(16x8), bf16 inputs, f32 accum
__device__ __forceinline__ void mma16816(float* d, const unsigned* a, unsigned b0, unsigned b1) {
    asm volatile(
        "mma.sync.aligned.m16n8k16.row.col.f32.bf16.bf16.f32 "
        "{%0,%1,%2,%3}, {%4,%5,%6,%7}, {%8,%9}, {%0,%1,%2,%3};\n"
        : "+f"(d[0]), "+f"(d[1]), "+f"(d[2]), "+f"(d[3])
        : "r"(a[0]), "r"(a[1]), "r"(a[2]), "r"(a[3]), "r"(b0), "r"(b1));
}

// ---------------------------------------------------------------------------
// Split fp32 -> (hi, lo) bf16, elementwise. x4 vectorized.
// ---------------------------------------------------------------------------
__global__ __launch_bounds__(256)
void split_kernel(const float* __restrict__ x, __nv_bfloat16* __restrict__ hi,
                  __nv_bfloat16* __restrict__ lo)
{
    int i = blockIdx.x * blockDim.x + threadIdx.x;   // float4 index
    float4 v = ((const float4*)x)[i];
    unsigned h01 = pk2(v.x, v.y), h23 = pk2(v.z, v.w);
    float r0 = v.x - lo_f32(h01), r1 = v.y - hi_f32(h01);
    float r2 = v.z - lo_f32(h23), r3 = v.w - hi_f32(h23);
    uint2 hw; hw.x = h01; hw.y = h23;
    uint2 lw; lw.x = pk2(r0, r1); lw.y = pk2(r2, r3);
    ((uint2*)hi)[i] = hw;
    ((uint2*)lo)[i] = lw;
}

// ---------------------------------------------------------------------------
// Tensor-core GEMM: C[M,N] = (A[M,K] @ W[N,K]^T + bias) * scale
// Split-bf16 3-pass. CTA 128x128, BK=32, 8 warps (4m x 2n), warp tile 32x64.
// mode 0: write fp32 to Cf.  mode 1: write split bf16 to Chi/Clo.
// ---------------------------------------------------------------------------
__global__ __launch_bounds__(256)
void gemm_tc_kernel(const __nv_bfloat16* __restrict__ Ahi, const __nv_bfloat16* __restrict__ Alo,
                    const __nv_bfloat16* __restrict__ Whi, const __nv_bfloat16* __restrict__ Wlo,
                    const float* __restrict__ bias,
                    float* __restrict__ Cf,
                    __nv_bfloat16* __restrict__ Chi, __nv_bfloat16* __restrict__ Clo,
                    float scale, int mode)
{
    __shared__ __nv_bfloat16 s_ah[128][40], s_al[128][40];
    __shared__ __nv_bfloat16 s_wh[128][40], s_wl[128][40];
    const int tid = threadIdx.x, warp = tid >> 5, lane = tid & 31;
    const int g = lane >> 2, t = lane & 3;
    const int wm = warp >> 1, wn = warp & 1;
    const int m0 = blockIdx.y << 7, n0 = blockIdx.x << 7;
    const int lr = tid >> 1, lj = (tid & 1) << 4;

    const __nv_bfloat16* ah_g = Ahi + (size_t)(m0 + lr) * DM + lj;
    const __nv_bfloat16* al_g = Alo + (size_t)(m0 + lr) * DM + lj;
    const __nv_bfloat16* wh_g = Whi + (size_t)(n0 + lr) * DM + lj;
    const __nv_bfloat16* wl_g = Wlo + (size_t)(n0 + lr) * DM + lj;

    float acc[2][8][4] = {};

    for (int k0 = 0; k0 < DM; k0 += 32) {
        uint4 va0 = *(const uint4*)(ah_g + k0), va1 = *(const uint4*)(ah_g + k0 + 8);
        uint4 vb0 = *(const uint4*)(al_g + k0), vb1 = *(const uint4*)(al_g + k0 + 8);
        uint4 vc0 = *(const uint4*)(wh_g + k0), vc1 = *(const uint4*)(wh_g + k0 + 8);
        uint4 vd0 = *(const uint4*)(wl_g + k0), vd1 = *(const uint4*)(wl_g + k0 + 8);
        __syncthreads();
        *(uint4*)&s_ah[lr][lj] = va0; *(uint4*)&s_ah[lr][lj + 8] = va1;
        *(uint4*)&s_al[lr][lj] = vb0; *(uint4*)&s_al[lr][lj + 8] = vb1;
        *(uint4*)&s_wh[lr][lj] = vc0; *(uint4*)&s_wh[lr][lj + 8] = vc1;
        *(uint4*)&s_wl[lr][lj] = vd0; *(uint4*)&s_wl[lr][lj + 8] = vd1;
        __syncthreads();
        #pragma unroll
        for (int kk = 0; kk < 2; kk++) {
            const int kw = kk << 3;
            unsigned ah[2][4], al[2][4];
            #pragma unroll
            for (int mt = 0; mt < 2; mt++) {
                const unsigned* pah = (const unsigned*)&s_ah[(wm << 5) + (mt << 4)][0];
                const unsigned* pal = (const unsigned*)&s_al[(wm << 5) + (mt << 4)][0];
                ah[mt][0] = pah[g * 20 + kw + t];
                ah[mt][1] = pah[(g + 8) * 20 + kw + t];
                ah[mt][2] = pah[g * 20 + kw + t + 4];
                ah[mt][3] = pah[(g + 8) * 20 + kw + t + 4];
                al[mt][0] = pal[g * 20 + kw + t];
                al[mt][1] = pal[(g + 8) * 20 + kw + t];
                al[mt][2] = pal[g * 20 + kw + t + 4];
                al[mt][3] = pal[(g + 8) * 20 + kw + t + 4];
            }
            #pragma unroll
            for (int nt = 0; nt < 8; nt++) {
                const unsigned* pwh = (const unsigned*)&s_wh[(wn << 6) + (nt << 3) + g][0];
                const unsigned* pwl = (const unsigned*)&s_wl[(wn << 6) + (nt << 3) + g][0];
                unsigned bh0 = pwh[kw + t], bh1 = pwh[kw + t + 4];
                unsigned bl0 = pwl[kw + t], bl1 = pwl[kw + t + 4];
                #pragma unroll
                for (int mt = 0; mt < 2; mt++) {
                    mma16816(acc[mt][nt], ah[mt], bh0, bh1);
                    mma16816(acc[mt][nt], ah[mt], bl0, bl1);
                    mma16816(acc[mt][nt], al[mt], bh0, bh1);
                }
            }
        }
    }

    #pragma unroll
    for (int mt = 0; mt < 2; mt++) {
        int r0 = m0 + (wm << 5) + (mt << 4) + g;
        #pragma unroll
        for (int nt = 0; nt < 8; nt++) {
            int c = n0 + (wn << 6) + (nt << 3) + (t << 1);
            float b0 = bias[c], b1 = bias[c + 1];
            float v0 = (acc[mt][nt][0] + b0) * scale;
            float v1 = (acc[mt][nt][1] + b1) * scale;
            float v2 = (acc[mt][nt][2] + b0) * scale;
            float v3 = (acc[mt][nt][3] + b1) * scale;
            if (mode == 0) {
                float2 w0, w1;
                w0.x = v0; w0.y = v1; w1.x = v2; w1.y = v3;
                *(float2*)&Cf[(size_t)r0 * DM + c] = w0;
                *(float2*)&Cf[(size_t)(r0 + 8) * DM + c] = w1;
            } else {
                unsigned h0 = pk2(v0, v1), h1 = pk2(v2, v3);
                unsigned l0 = pk2(v0 - lo_f32(h0), v1 - hi_f32(h0));
                unsigned l1 = pk2(v2 - lo_f32(h1), v3 - hi_f32(h1));
                ((unsigned*)Chi)[((size_t)r0 * DM + c) >> 1] = h0;
                ((unsigned*)Chi)[((size_t)(r0 + 8) * DM + c) >> 1] = h1;
                ((unsigned*)Clo)[((size_t)r0 * DM + c) >> 1] = l0;
                ((unsigned*)Clo)[((size_t)(r0 + 8) * DM + c) >> 1] = l1;
            }
        }
    }
}

// ---------------------------------------------------------------------------
// Tensor-core flash attention, split-bf16 3-pass mma (proven R7 core).
// CTA = 128 queries of one (b,h); 8 warps; KV tile 64.
// Epilogue now emits split bf16 (feeds the O-projection gemm_tc).
// ---------------------------------------------------------------------------
__global__ __launch_bounds__(256)
void flash_kernel(const __nv_bfloat16* __restrict__ qhi, const __nv_bfloat16* __restrict__ qlo,
                  const __nv_bfloat16* __restrict__ khi, const __nv_bfloat16* __restrict__ klo,
                  const __nv_bfloat16* __restrict__ vhi, const __nv_bfloat16* __restrict__ vlo,
                  __nv_bfloat16* __restrict__ ohi, __nv_bfloat16* __restrict__ olo)
{
    __shared__ __nv_bfloat16 s_khi[64][72], s_klo[64][72];
    __shared__ __nv_bfloat16 s_vhi[64][72], s_vlo[64][72];

    const int tid = threadIdx.x;
    const int warp = tid >> 5, lane = tid & 31;
    const int g = lane >> 2, t = lane & 3;
    const int bh = blockIdx.y;
    const int b = bh / NH, h = bh - b * NH;
    const int q0 = blockIdx.x << 7;

    const size_t base = (size_t)b * SQ * DM + (size_t)h * DKH;

    unsigned aQh[4][4], aQl[4][4];
    {
        const unsigned* qh  = (const unsigned*)(qhi + base + (size_t)(q0 + (warp << 4) + g) * DM);
        const unsigned* qh8 = qh + 8 * DM / 2;
        const unsigned* ql  = (const unsigned*)(qlo + base + (size_t)(q0 + (warp << 4) + g) * DM);
        const unsigned* ql8 = ql + 8 * DM / 2;
        #pragma unroll
        for (int kt = 0; kt < 4; kt++) {
            aQh[kt][0] = qh [8 * kt + t];
            aQh[kt][1] = qh8[8 * kt + t];
            aQh[kt][2] = qh [8 * kt + t + 4];
            aQh[kt][3] = qh8[8 * kt + t + 4];
            aQl[kt][0] = ql [8 * kt + t];
            aQl[kt][1] = ql8[8 * kt + t];
            aQl[kt][2] = ql [8 * kt + t + 4];
            aQl[kt][3] = ql8[8 * kt + t + 4];
        }
    }

    float m0 = -1e30f, m1 = -1e30f, l0 = 0.f, l1 = 0.f;
    float oacc[8][4] = {};

    const __nv_bfloat16* kh_g = khi + base;
    const __nv_bfloat16* kl_g = klo + base;
    const __nv_bfloat16* vh_g = vhi + base;
    const __nv_bfloat16* vl_g = vlo + base;

    for (int kv0 = 0; kv0 < SQ; kv0 += 64) {
        __syncthreads();
        #pragma unroll
        for (int it = 0; it < 2; it++) {
            int i = tid + it * 256;
            int r = i >> 3, j = i & 7;
            size_t gofs = (size_t)(kv0 + r) * DM;
            *((uint4*)&s_khi[r][0] + j) = *((const uint4*)(kh_g + gofs) + j);
            *((uint4*)&s_klo[r][0] + j) = *((const uint4*)(kl_g + gofs) + j);
            *((uint4*)&s_vhi[r][0] + j) = *((const uint4*)(vh_g + gofs) + j);
            *((uint4*)&s_vlo[r][0] + j) = *((const uint4*)(vl_g + gofs) + j);
        }
        __syncthreads();

        float s[8][4] = {};
        #pragma unroll
        for (int kt = 0; kt < 4; kt++)
            #pragma unroll
            for (int nt = 0; nt < 8; nt++) {
                const unsigned* krh = (const unsigned*)&s_khi[8 * nt + g][0];
                const unsigned* krl = (const unsigned*)&s_klo[8 * nt + g][0];
                unsigned bh0 = krh[8 * kt + t], bh1 = krh[8 * kt + t + 4];
                unsigned bl0 = krl[8 * kt + t], bl1 = krl[8 * kt + t + 4];
                mma16816(s[nt], aQh[kt], bh0, bh1);
                mma16816(s[nt], aQh[kt], bl0, bl1);
                mma16816(s[nt], aQl[kt], bh0, bh1);
            }

        float mx0 = -1e30f, mx1 = -1e30f;
        #pragma unroll
        for (int nt = 0; nt < 8; nt++) {
            mx0 = fmaxf(mx0, fmaxf(s[nt][0], s[nt][1]));
            mx1 = fmaxf(mx1, fmaxf(s[nt][2], s[nt][3]));
        }
        mx0 = fmaxf(mx0, __shfl_xor_sync(0xffffffffu, mx0, 1));
        mx0 = fmaxf(mx0, __shfl_xor_sync(0xffffffffu, mx0, 2));
        mx1 = fmaxf(mx1, __shfl_xor_sync(0xffffffffu, mx1, 1));
        mx1 = fmaxf(mx1, __shfl_xor_sync(0xffffffffu, mx1, 2));
        float mn0 = fmaxf(m0, mx0), mn1 = fmaxf(m1, mx1);
        float al0 = __expf(m0 - mn0), al1 = __expf(m1 - mn1);
        m0 = mn0; m1 = mn1;
        float ls0 = 0.f, ls1 = 0.f;
        #pragma unroll
        for (int nt = 0; nt < 8; nt++) {
            s[nt][0] = __expf(s[nt][0] - mn0); ls0 += s[nt][0];
            s[nt][1] = __expf(s[nt][1] - mn0); ls0 += s[nt][1];
            s[nt][2] = __expf(s[nt][2] - mn1); ls1 += s[nt][2];
            s[nt][3] = __expf(s[nt][3] - mn1); ls1 += s[nt][3];
        }
        ls0 += __shfl_xor_sync(0xffffffffu, ls0, 1);
        ls0 += __shfl_xor_sync(0xffffffffu, ls0, 2);
        ls1 += __shfl_xor_sync(0xffffffffu, ls1, 1);
        ls1 += __shfl_xor_sync(0xffffffffu, ls1, 2);
        l0 = l0 * al0 + ls0;
        l1 = l1 * al1 + ls1;
        #pragma unroll
        for (int nt = 0; nt < 8; nt++) {
            oacc[nt][0] *= al0; oacc[nt][1] *= al0;
            oacc[nt][2] *= al1; oacc[nt][3] *= al1;
        }

        unsigned pah[4][4], pal[4][4];
        #pragma unroll
        for (int kt = 0; kt < 4; kt++) {
            int e = 2 * kt, od = 2 * kt + 1;
            pah[kt][0] = pk2(s[e][0],  s[e][1]);
            pah[kt][1] = pk2(s[e][2],  s[e][3]);
            pah[kt][2] = pk2(s[od][0], s[od][1]);
            pah[kt][3] = pk2(s[od][2], s[od][3]);
            pal[kt][0] = pk2(s[e][0]  - lo_f32(pah[kt][0]), s[e][1]  - hi_f32(pah[kt][0]));
            pal[kt][1] = pk2(s[e][2]  - lo_f32(pah[kt][1]), s[e][3]  - hi_f32(pah[kt][1]));
            pal[kt][2] = pk2(s[od][0] - lo_f32(pah[kt][2]), s[od][1] - hi_f32(pah[kt][2]));
            pal[kt][3] = pk2(s[od][2] - lo_f32(pah[kt][3]), s[od][3] - hi_f32(pah[kt][3]));
        }

        #pragma unroll
        for (int kt = 0; kt < 4; kt++) {
            int kr = 16 * kt + 2 * t;
            #pragma unroll
            for (int nt = 0; nt < 8; nt++) {
                int c = 8 * nt + g;
                unsigned vh0a = *(const unsigned short*)&s_vhi[kr][c];
                unsigned vh0b = *(const unsigned short*)&s_vhi[kr + 1][c];
                unsigned vh1a = *(const unsigned short*)&s_vhi[kr + 8][c];
                unsigned vh1b = *(const unsigned short*)&s_vhi[kr + 9][c];
                unsigned vl0a = *(const unsigned short*)&s_vlo[kr][c];
                unsigned vl0b = *(const unsigned short*)&s_vlo[kr + 1][c];
                unsigned vl1a = *(const unsigned short*)&s_vlo[kr + 8][c];
                unsigned vl1b = *(const unsigned short*)&s_vlo[kr + 9][c];
                unsigned bh0 = vh0a | (vh0b << 16);
                unsigned bh1 = vh1a | (vh1b << 16);
                unsigned bl0 = vl0a | (vl0b << 16);
                unsigned bl1 = vl1a | (vl1b << 16);
                mma16816(oacc[nt], pah[kt], bh0, bh1);
                mma16816(oacc[nt], pah[kt], bl0, bl1);
                mma16816(oacc[nt], pal[kt], bh0, bh1);
            }
        }
    }

    // epilogue: normalize, split to bf16 hi/lo, write combined layout (B,S,H*dk)
    float inv0 = 1.0f / l0, inv1 = 1.0f / l1;
    unsigned* oh0 = (unsigned*)(ohi + base + (size_t)(q0 + (warp << 4) + g) * DM);
    unsigned* oh1 = oh0 + 4 * DM;
    unsigned* ol0 = (unsigned*)(olo + base + (size_t)(q0 + (warp << 4) + g) * DM);
    unsigned* ol1 = ol0 + 4 * DM;
    #pragma unroll
    for (int nt = 0; nt < 8; nt++) {
        float v0 = oacc[nt][0] * inv0, v1 = oacc[nt][1] * inv0;
        float v2 = oacc[nt][2] * inv1, v3 = oacc[nt][3] * inv1;
        unsigned h0 = pk2(v0, v1), h1 = pk2(v2, v3);
        unsigned lw0 = pk2(v0 - lo_f32(h0), v1 - hi_f32(h0));
        unsigned lw1 = pk2(v2 - lo_f32(h1), v3 - hi_f32(h1));
        oh0[4 * nt + t] = h0; oh1[4 * nt + t] = h1;
        ol0[4 * nt + t] = lw0; ol1[4 * nt + t] = lw1;
    }
}

// ---------------------------------------------------------------------------
extern "C" void kernel_launch(void* const* d_in, const int* in_sizes, int n_in,
                              void* d_out, int out_size)
{
    const float* Q  = (const float*)d_in[0];
    const float* K  = (const float*)d_in[1];
    const float* V  = (const float*)d_in[2];
    const float* Wq = (const float*)d_in[3];
    const float* bq = (const float*)d_in[4];
    const float* Wk = (const float*)d_in[5];
    const float* bk = (const float*)d_in[6];
    const float* Wv = (const float*)d_in[7];
    const float* bv = (const float*)d_in[8];
    const float* Wo = (const float*)d_in[9];
    const float* bo = (const float*)d_in[10];
    float* out = (float*)d_out;

    __nv_bfloat16 *iqh, *iql, *ikh, *ikl, *ivh, *ivl;
    __nv_bfloat16 *wqh, *wql, *wkh, *wkl, *wvh, *wvl, *woh, *wol;
    __nv_bfloat16 *pqh, *pql, *pkh, *pkl, *pvh, *pvl, *ath, *atl;
    cudaGetSymbolAddress((void**)&iqh, g_iqh); cudaGetSymbolAddress((void**)&iql, g_iql);
    cudaGetSymbolAddress((void**)&ikh, g_ikh); cudaGetSymbolAddress((void**)&ikl, g_ikl);
    cudaGetSymbolAddress((void**)&ivh, g_ivh); cudaGetSymbolAddress((void**)&ivl, g_ivl);
    cudaGetSymbolAddress((void**)&wqh, g_wqh); cudaGetSymbolAddress((void**)&wql, g_wql);
    cudaGetSymbolAddress((void**)&wkh, g_wkh); cudaGetSymbolAddress((void**)&wkl, g_wkl);
    cudaGetSymbolAddress((void**)&wvh, g_wvh); cudaGetSymbolAddress((void**)&wvl, g_wvl);
    cudaGetSymbolAddress((void**)&woh, g_woh); cudaGetSymbolAddress((void**)&wol, g_wol);
    cudaGetSymbolAddress((void**)&pqh, g_pqh); cudaGetSymbolAddress((void**)&pql, g_pql);
    cudaGetSymbolAddress((void**)&pkh, g_pkh); cudaGetSymbolAddress((void**)&pkl, g_pkl);
    cudaGetSymbolAddress((void**)&pvh, g_pvh); cudaGetSymbolAddress((void**)&pvl, g_pvl);
    cudaGetSymbolAddress((void**)&ath, g_ath); cudaGetSymbolAddress((void**)&atl, g_atl);

    const int nsp  = (NT * DM) / 4 / 256;   // 6144 blocks (inputs)
    const int nspw = (DM * DM) / 4 / 256;   // 576 blocks (weights)

    split_kernel<<<nsp, 256>>>(Q, iqh, iql);
    split_kernel<<<nsp, 256>>>(K, ikh, ikl);
    split_kernel<<<nsp, 256>>>(V, ivh, ivl);
    split_kernel<<<nspw, 256>>>(Wq, wqh, wql);
    split_kernel<<<nspw, 256>>>(Wk, wkh, wkl);
    split_kernel<<<nspw, 256>>>(Wv, wvh, wvl);
    split_kernel<<<nspw, 256>>>(Wo, woh, wol);

    dim3 gg(DM / 128, NT / 128);   // (6, 64)
    gemm_tc_kernel<<<gg, 256>>>(iqh, iql, wqh, wql, bq, nullptr, pqh, pql, 0.125f, 1);
    gemm_tc_kernel<<<gg, 256>>>(ikh, ikl, wkh, wkl, bk, nullptr, pkh, pkl, 1.0f, 1);
    gemm_tc_kernel<<<gg, 256>>>(ivh, ivl, wvh, wvl, bv, nullptr, pvh, pvl, 1.0f, 1);

    dim3 fg(SQ / 128, NB * NH);    // (32, 24)
    flash_kernel<<<fg, 256>>>(pqh, pql, pkh, pkl, pvh, pvl, ath, atl);

    gemm_tc_kernel<<<gg, 256>>>(ath, atl, woh, wol, bo, out, nullptr, nullptr, 1.0f, 0);
}